// round 9
// baseline (speedup 1.0000x reference)
#include <cuda_runtime.h>

// Problem constants
#define BB     16
#define NCTX   1024
#define NG     64          // grid points per axis (NX == NY == 64)
#define MROWS  192         // 64 i-rows * 3 channels
#define KSPL   8           // split-K factor
#define KCH    (NCTX/KSPL) // 128 n per CTA
#define KPAD   (KCH + 1)   // +1 row so depth-1 prefetch of k+1 stays in-bounds

typedef unsigned long long u64;

// split-K partial results: [b][ks][m=192][j=64]
__device__ float g_partial[BB * KSPL * MROWS * NG];

__device__ __forceinline__ void unpack2(u64 v, float& lo, float& hi) {
    unsigned a, b;
    asm("mov.b64 {%0, %1}, %2;" : "=r"(a), "=r"(b) : "l"(v));
    lo = __uint_as_float(a);
    hi = __uint_as_float(b);
}
__device__ __forceinline__ u64 mul2(u64 a, u64 b) {
    u64 d;
    asm("mul.rn.f32x2 %0, %1, %2;" : "=l"(d) : "l"(a), "l"(b));
    return d;
}
__device__ __forceinline__ u64 fma2(u64 a, u64 b, u64 c) {
    u64 d;
    asm("fma.rn.f32x2 %0, %1, %2, %3;" : "=l"(d) : "l"(a), "l"(b), "l"(c));
    return d;
}

// ---------------------------------------------------------------------------
// Kernel A: fused exp + per-batch split-K GEMM, f32x2 FMA, 512 threads/CTA.
//   Pd[n,2j] = Pd[n,2j+1] = exp(-0.5*(xs[j]-Xx)^2/l^2)   (pre-duplicated)
//   Q [n,i]  = exp(-0.5*(ys[i]-Xy)^2/l^2)
//   eyd[n]   = {y0,y0,y1,y1}
//   C[i*3+c, j] += sum_n Q[n,i]*ey_c[n]*P[n,j]
// Thread tile: 6 m-rows (i pair 2r,2r+1 x 3 ch) x 4 j-cols.
// Manual depth-1 prefetch, k-loop NOT unrolled => load regs stay at one
// buffer pair (~14 regs) and total regs ~80 (no spill; 16 warps/CTA hide LDS).
// ---------------------------------------------------------------------------
__global__ void __launch_bounds__(512, 1)
equiv_gemm_kernel(const float* __restrict__ X,
                  const float* __restrict__ Y,
                  const float* __restrict__ lls)
{
    extern __shared__ float sm[];
    float* Pd_sm = sm;                               // [KPAD][128] dup pairs
    float* Q_sm  = sm + KPAD * 128;                  // [KPAD][64]
    float* eyd   = sm + KPAD * 128 + KPAD * 64;      // [KPAD][4] {y0,y0,y1,y1}

    const int ks  = blockIdx.x;
    const int b   = blockIdx.y;
    const int tid = threadIdx.x;
    const int n0  = ks * KCH;

    const float invl2 = __expf(-2.0f * lls[0]);   // 1 / l^2
    const float step  = 20.0f / 63.0f;

    // ---- Phase A: Pd (duplicated), Q, eyd. Four threads per n-row. ----
    {
        const int nl = tid >> 2;           // 128 rows
        const int wh = tid & 3;
        const int j0 = wh * 16;
        const int n  = b * NCTX + n0 + nl;
        const float xx = X[2 * n];
        const float xy = X[2 * n + 1];
        float* pr = Pd_sm + nl * 128;
        float* qr = Q_sm + nl * 64;
        #pragma unroll 8
        for (int j = j0; j < j0 + 16; ++j) {
            const float gx = -10.0f + (float)j * step;   // xs[j]
            const float gy =  10.0f - (float)j * step;   // ys[i]
            const float dx = gx - xx;
            const float dy = gy - xy;
            const float p  = __expf(-0.5f * dx * dx * invl2);
            pr[2 * j]     = p;
            pr[2 * j + 1] = p;
            qr[j] = __expf(-0.5f * dy * dy * invl2);
        }
        if (wh < 2) {
            const float yv = Y[2 * n + wh];
            eyd[nl * 4 + 2 * wh]     = yv;
            eyd[nl * 4 + 2 * wh + 1] = yv;
        }
    }
    __syncthreads();

    // ---- Phase B: GEMM with f32x2 packed FMA ----
    const int r  = tid & 31;          // m-tile: rows 6r..6r+5 (i = 2r, 2r+1)
    const int jb = (tid >> 5) * 4;    // 16 warps x 4 j-cols = 64

    u64 acc[3][4];
    #pragma unroll
    for (int c = 0; c < 3; ++c)
        #pragma unroll
        for (int v = 0; v < 4; ++v)
            acc[c][v] = 0ULL;

    const float* qp  = Q_sm + 2 * r;
    const float* ppd = Pd_sm + 2 * jb;

    // prefetch k=0 (qq coalesced LDS.64; ey/p broadcast LDS.128)
    u64        qq = *(const u64*)qp;
    ulonglong2 ey = *(const ulonglong2*)eyd;
    ulonglong2 pA = *(const ulonglong2*)ppd;
    ulonglong2 pB = *(const ulonglong2*)(ppd + 4);

    #pragma unroll 1
    for (int k = 0; k < KCH; ++k) {
        const u64        qq_c = qq;
        const ulonglong2 ey_c = ey;
        const u64 pd[4] = {pA.x, pA.y, pB.x, pB.y};

        // prefetch k+1 (padded row keeps this in-bounds at k = KCH-1)
        qq = *(const u64*)(qp + (k + 1) * 64);
        ey = *(const ulonglong2*)(eyd + (k + 1) * 4);
        pA = *(const ulonglong2*)(ppd + (k + 1) * 128);
        pB = *(const ulonglong2*)(ppd + (k + 1) * 128 + 4);

        const u64 m1 = mul2(qq_c, ey_c.x);   // {q0*y0, q1*y0}
        const u64 m2 = mul2(qq_c, ey_c.y);   // {q0*y1, q1*y1}

        #pragma unroll
        for (int v = 0; v < 4; ++v) {
            acc[0][v] = fma2(qq_c, pd[v], acc[0][v]);
            acc[1][v] = fma2(m1,   pd[v], acc[1][v]);
            acc[2][v] = fma2(m2,   pd[v], acc[2][v]);
        }
    }
    __syncthreads();

    // ---- Epilogue: stage C in smem (reuse Pd region), coalesced store ----
    float* C_sm = sm;   // 192*64 = 12288 floats
    #pragma unroll
    for (int c = 0; c < 3; ++c)
        #pragma unroll
        for (int v = 0; v < 4; ++v) {
            float lo, hi;
            unpack2(acc[c][v], lo, hi);
            C_sm[(6 * r + c)     * 64 + jb + v] = lo;   // i = 2r
            C_sm[(6 * r + 3 + c) * 64 + jb + v] = hi;   // i = 2r+1
        }
    __syncthreads();

    float4* dst = (float4*)(g_partial + (size_t)(b * KSPL + ks) * (MROWS * NG));
    const float4* src = (const float4*)C_sm;
    #pragma unroll
    for (int idx = tid; idx < MROWS * NG / 4; idx += 512)
        dst[idx] = src[idx];
}

// ---------------------------------------------------------------------------
// Kernel B: reduce split-K partials. One thread per (channel, b, i, j4).
// Channels 1/2 re-read channel-0 partials for the density divide (L2-hot).
// ---------------------------------------------------------------------------
__global__ void __launch_bounds__(128)
equiv_reduce_kernel(float* __restrict__ out)
{
    const int t   = blockIdx.x * 128 + threadIdx.x;   // 49152
    const int ch  = t >> 14;                          // 0..2
    const int rem = t & 16383;                        // b*1024 + i*16 + j4idx
    const int b   = rem >> 10;
    const int pos = rem & 1023;
    const int i   = pos >> 4;
    const int j4  = (pos & 15) * 4;

    const float* base = g_partial + ((size_t)b * KSPL * MROWS + i * 3) * NG + j4;

    float4 s = make_float4(0.f, 0.f, 0.f, 0.f);
    #pragma unroll
    for (int sk = 0; sk < KSPL; ++sk) {
        const float4 v = *(const float4*)(base + (size_t)sk * MROWS * NG + ch * NG);
        s.x += v.x; s.y += v.y; s.z += v.z; s.w += v.w;
    }

    float4 o = s;
    if (ch != 0) {
        float4 d = make_float4(0.f, 0.f, 0.f, 0.f);
        #pragma unroll
        for (int sk = 0; sk < KSPL; ++sk) {
            const float4 v = *(const float4*)(base + (size_t)sk * MROWS * NG);
            d.x += v.x; d.y += v.y; d.z += v.z; d.w += v.w;
        }
        o = make_float4(s.x / d.x, s.y / d.y, s.z / d.z, s.w / d.w);
    }

    *(float4*)&out[(b * 3 + ch) * 4096 + i * 64 + j4] = o;
}

// ---------------------------------------------------------------------------
extern "C" void kernel_launch(void* const* d_in, const int* in_sizes, int n_in,
                              void* d_out, int out_size)
{
    const float* X   = (const float*)d_in[0];
    const float* Y   = (const float*)d_in[1];
    const float* lls = (const float*)d_in[2];
    float* out = (float*)d_out;

    const size_t smem_bytes = (size_t)(KPAD * 128 + KPAD * 64 + KPAD * 4) * sizeof(float); // ~101KB
    cudaFuncSetAttribute(equiv_gemm_kernel,
                         cudaFuncAttributeMaxDynamicSharedMemorySize,
                         (int)smem_bytes);

    equiv_gemm_kernel<<<dim3(KSPL, BB), 512, smem_bytes>>>(X, Y, lls);
    equiv_reduce_kernel<<<(3 * BB * NG * NG / 4) / 128, 128>>>(out);
}

// round 10
// speedup vs baseline: 1.2821x; 1.2821x over previous
#include <cuda_runtime.h>

// Problem constants
#define BB     16
#define NCTX   1024
#define NG     64          // grid points per axis (NX == NY == 64)
#define MROWS  192         // 64 i-rows * 3 channels
#define KSPL   16          // split-K factor (2 CTAs per SM co-resident)
#define KCH    (NCTX/KSPL) // 64 n per CTA

typedef unsigned long long u64;

// split-K partial results: [b][ks][m=192][j=64]
__device__ float g_partial[BB * KSPL * MROWS * NG];

__device__ __forceinline__ u64 pack2(float lo, float hi) {
    u64 d;
    asm("mov.b64 %0, {%1, %2};" : "=l"(d)
        : "r"(__float_as_uint(lo)), "r"(__float_as_uint(hi)));
    return d;
}
__device__ __forceinline__ void unpack2(u64 v, float& lo, float& hi) {
    unsigned a, b;
    asm("mov.b64 {%0, %1}, %2;" : "=r"(a), "=r"(b) : "l"(v));
    lo = __uint_as_float(a);
    hi = __uint_as_float(b);
}
__device__ __forceinline__ u64 mul2(u64 a, u64 b) {
    u64 d;
    asm("mul.rn.f32x2 %0, %1, %2;" : "=l"(d) : "l"(a), "l"(b));
    return d;
}
__device__ __forceinline__ u64 fma2(u64 a, u64 b, u64 c) {
    u64 d;
    asm("fma.rn.f32x2 %0, %1, %2, %3;" : "=l"(d) : "l"(a), "l"(b), "l"(c));
    return d;
}

// ---------------------------------------------------------------------------
// Kernel A: fused exp + per-batch split-K GEMM with packed f32x2 FMA.
// EXACT R6 inner-loop structure (proven fastest); only KCH halved (64) and
// occupancy raised to 2 CTAs/SM so the second CTA hides exp/epilogue/LDS
// bubbles of the first.
//   P[n, j] = exp(-0.5*(xs[j]-Xx)^2/l^2)
//   Q[n, i] = exp(-0.5*(ys[i]-Xy)^2/l^2)
//   C[i*3+c, j] += sum_n Q[n,i] * ey_c[n] * P[n,j]   (ey = {1, y0, y1})
// Thread tile: 6 m-rows (i pair 2r,2r+1 x 3 channels) x 8 j-cols.
// ---------------------------------------------------------------------------
__global__ void __launch_bounds__(256, 2)
equiv_gemm_kernel(const float* __restrict__ X,
                  const float* __restrict__ Y,
                  const float* __restrict__ lls)
{
    extern __shared__ float sm[];
    float* P_sm  = sm;                 // [KCH][64]
    float* Q_sm  = sm + KCH * 64;      // [KCH][64]
    float* ey_sm = sm + 2 * KCH * 64;  // [KCH][2]

    const int ks  = blockIdx.x;
    const int b   = blockIdx.y;
    const int tid = threadIdx.x;
    const int n0  = ks * KCH;

    const float invl2 = __expf(-2.0f * lls[0]);   // 1 / l^2
    const float step  = 20.0f / 63.0f;

    // ---- Phase A: P and Q. Four threads per n-row (64 rows), 16 j each. ----
    {
        const int nl = tid >> 2;
        const int j0 = (tid & 3) * 16;
        const int n  = b * NCTX + n0 + nl;
        const float xx = X[2 * n];
        const float xy = X[2 * n + 1];
        float* prow = P_sm + nl * 64;
        float* qrow = Q_sm + nl * 64;
        #pragma unroll 8
        for (int j = j0; j < j0 + 16; ++j) {
            const float gx = -10.0f + (float)j * step;   // xs[j]
            const float gy =  10.0f - (float)j * step;   // ys[i]
            const float dx = gx - xx;
            const float dy = gy - xy;
            prow[j] = __expf(-0.5f * dx * dx * invl2);
            qrow[j] = __expf(-0.5f * dy * dy * invl2);
        }
        // ey: 128 contiguous floats (y0,y1 pairs for 64 rows)
        if (tid < 2 * KCH)
            ey_sm[tid] = Y[(b * NCTX + n0) * 2 + tid];
    }
    __syncthreads();

    // ---- Phase B: GEMM with f32x2 packed FMA (R6-identical) ----
    const int r  = tid & 31;    // m-tile: rows 6r .. 6r+5  (i = 2r, 2r+1)
    const int q  = tid >> 5;    // j-tile: cols 8q .. 8q+7
    const int jb = q * 8;

    u64 acc[3][8];
    #pragma unroll
    for (int c = 0; c < 3; ++c)
        #pragma unroll
        for (int v = 0; v < 8; ++v)
            acc[c][v] = 0ULL;

    // prefetch k=0
    u64    qq = *(const u64*)&Q_sm[2 * r];
    float2 yv = *(const float2*)&ey_sm[0];
    float4 pa = *(const float4*)&P_sm[jb];
    float4 pb = *(const float4*)&P_sm[jb + 4];

    #pragma unroll 2
    for (int k = 0; k < KCH; ++k) {
        const u64    qq_c = qq;
        const float2 yv_c = yv;
        const float4 pa_c = pa;
        const float4 pb_c = pb;
        if (k + 1 < KCH) {
            qq = *(const u64*)&Q_sm[(k + 1) * 64 + 2 * r];
            yv = *(const float2*)&ey_sm[2 * (k + 1)];
            pa = *(const float4*)&P_sm[(k + 1) * 64 + jb];
            pb = *(const float4*)&P_sm[(k + 1) * 64 + jb + 4];
        }

        const u64 yd0 = pack2(yv_c.x, yv_c.x);
        const u64 yd1 = pack2(yv_c.y, yv_c.y);
        const u64 m1  = mul2(qq_c, yd0);   // {q0*y0, q1*y0}
        const u64 m2  = mul2(qq_c, yd1);   // {q0*y1, q1*y1}

        const float pv[8] = {pa_c.x, pa_c.y, pa_c.z, pa_c.w,
                             pb_c.x, pb_c.y, pb_c.z, pb_c.w};
        #pragma unroll
        for (int v = 0; v < 8; ++v) {
            const u64 pd = pack2(pv[v], pv[v]);
            acc[0][v] = fma2(qq_c, pd, acc[0][v]);
            acc[1][v] = fma2(m1,   pd, acc[1][v]);
            acc[2][v] = fma2(m2,   pd, acc[2][v]);
        }
    }
    __syncthreads();

    // ---- Epilogue: stage C in smem (reuse P/Q region), coalesced store ----
    float* C_sm = sm;   // 192*64 = 12288 floats > 8320 avail? NO: smem is 8320
    // NOTE: smem region is (2*KCH*64 + 2*KCH) = 8320 floats at KCH=64, but C
    // needs 12288. Stage C in two halves (96 rows each) to stay in-bounds.
    #pragma unroll
    for (int half = 0; half < 2; ++half) {
        // rows [half*96, half*96+96): this thread owns rows 6r+c, 6r+3+c
        #pragma unroll
        for (int c = 0; c < 3; ++c)
            #pragma unroll
            for (int v = 0; v < 8; ++v) {
                float lo, hi;
                unpack2(acc[c][v], lo, hi);
                const int row0 = 6 * r + c;        // i = 2r
                const int row1 = 6 * r + 3 + c;    // i = 2r+1
                if (row0 >= half * 96 && row0 < half * 96 + 96)
                    C_sm[(row0 - half * 96) * 64 + jb + v] = lo;
                if (row1 >= half * 96 && row1 < half * 96 + 96)
                    C_sm[(row1 - half * 96) * 64 + jb + v] = hi;
            }
        __syncthreads();
        float4* dst = (float4*)(g_partial +
            (size_t)(b * KSPL + ks) * (MROWS * NG) + half * 96 * 64);
        const float4* src = (const float4*)C_sm;
        #pragma unroll
        for (int idx = tid; idx < 96 * 64 / 4; idx += 256)
            dst[idx] = src[idx];
        __syncthreads();
    }
}

// ---------------------------------------------------------------------------
// Kernel B: reduce split-K partials. One thread per (channel, b, i, j4).
// Channels 1/2 re-read channel-0 partials for the density divide (L2-hot).
// ---------------------------------------------------------------------------
__global__ void __launch_bounds__(128)
equiv_reduce_kernel(float* __restrict__ out)
{
    const int t   = blockIdx.x * 128 + threadIdx.x;   // 49152
    const int ch  = t >> 14;                          // 0..2
    const int rem = t & 16383;                        // b*1024 + i*16 + j4idx
    const int b   = rem >> 10;
    const int pos = rem & 1023;
    const int i   = pos >> 4;
    const int j4  = (pos & 15) * 4;

    const float* base = g_partial + ((size_t)b * KSPL * MROWS + i * 3) * NG + j4;

    float4 s = make_float4(0.f, 0.f, 0.f, 0.f);
    #pragma unroll
    for (int sk = 0; sk < KSPL; ++sk) {
        const float4 v = *(const float4*)(base + (size_t)sk * MROWS * NG + ch * NG);
        s.x += v.x; s.y += v.y; s.z += v.z; s.w += v.w;
    }

    float4 o = s;
    if (ch != 0) {
        float4 d = make_float4(0.f, 0.f, 0.f, 0.f);
        #pragma unroll
        for (int sk = 0; sk < KSPL; ++sk) {
            const float4 v = *(const float4*)(base + (size_t)sk * MROWS * NG);
            d.x += v.x; d.y += v.y; d.z += v.z; d.w += v.w;
        }
        o = make_float4(s.x / d.x, s.y / d.y, s.z / d.z, s.w / d.w);
    }

    *(float4*)&out[(b * 3 + ch) * 4096 + i * 64 + j4] = o;
}

// ---------------------------------------------------------------------------
extern "C" void kernel_launch(void* const* d_in, const int* in_sizes, int n_in,
                              void* d_out, int out_size)
{
    const float* X   = (const float*)d_in[0];
    const float* Y   = (const float*)d_in[1];
    const float* lls = (const float*)d_in[2];
    float* out = (float*)d_out;

    const size_t smem_bytes = (size_t)(2 * KCH * 64 + 2 * KCH) * sizeof(float); // 33280
    cudaFuncSetAttribute(equiv_gemm_kernel,
                         cudaFuncAttributeMaxDynamicSharedMemorySize,
                         (int)smem_bytes);

    equiv_gemm_kernel<<<dim3(KSPL, BB), 256, smem_bytes>>>(X, Y, lls);
    equiv_reduce_kernel<<<(3 * BB * NG * NG / 4) / 128, 128>>>(out);
}